// round 2
// baseline (speedup 1.0000x reference)
#include <cuda_runtime.h>
#include <math.h>

#define HEADS 16
#define DIM 64
#define NTOK 2048
#define CHID 1024
#define BATCH 2
#define SCALE 0.125f
#define MASKV -10000.0f

// scratch: [qkv][b][h][n][d]  (3*2*16*2048*64 floats = 48MB)
__device__ float g_qkv[3UL * BATCH * HEADS * NTOK * DIM];

// ---------------- QKV projection GEMM ----------------
// C[m][o] = sum_k X[m][k] * W[o][k];  M=4096, N=3072, K=1024
__global__ __launch_bounds__(256) void qkv_gemm_kernel(const float* __restrict__ X,
                                                       const float* __restrict__ Wt) {
    __shared__ float As[16][128];
    __shared__ float Bs[16][128];
    const int K = 1024;
    int t = threadIdx.x;
    int bm = blockIdx.y, bn = blockIdx.x;
    int tr = t >> 4, tc = t & 15;
    int lrow = t >> 2;            // 0..63
    int lk = (t & 3) << 2;        // 0,4,8,12
    int sx = (lk >> 2) << 3;      // store swizzle 0,8,16,24

    const float* Ag = X + (size_t)(bm * 128 + lrow) * K + lk;
    const float* Bg = Wt + (size_t)(bn * 128 + lrow) * K + lk;

    float acc[8][8];
#pragma unroll
    for (int i = 0; i < 8; i++)
#pragma unroll
        for (int j = 0; j < 8; j++) acc[i][j] = 0.f;

    for (int k0 = 0; k0 < K; k0 += 16) {
        float4 a0 = *(const float4*)(Ag + k0);
        float4 a1 = *(const float4*)(Ag + (size_t)64 * K + k0);
        float4 b0 = *(const float4*)(Bg + k0);
        float4 b1 = *(const float4*)(Bg + (size_t)64 * K + k0);
        As[lk + 0][lrow ^ sx] = a0.x;
        As[lk + 1][lrow ^ sx] = a0.y;
        As[lk + 2][lrow ^ sx] = a0.z;
        As[lk + 3][lrow ^ sx] = a0.w;
        As[lk + 0][(lrow + 64) ^ sx] = a1.x;
        As[lk + 1][(lrow + 64) ^ sx] = a1.y;
        As[lk + 2][(lrow + 64) ^ sx] = a1.z;
        As[lk + 3][(lrow + 64) ^ sx] = a1.w;
        Bs[lk + 0][lrow ^ sx] = b0.x;
        Bs[lk + 1][lrow ^ sx] = b0.y;
        Bs[lk + 2][lrow ^ sx] = b0.z;
        Bs[lk + 3][lrow ^ sx] = b0.w;
        Bs[lk + 0][(lrow + 64) ^ sx] = b1.x;
        Bs[lk + 1][(lrow + 64) ^ sx] = b1.y;
        Bs[lk + 2][(lrow + 64) ^ sx] = b1.z;
        Bs[lk + 3][(lrow + 64) ^ sx] = b1.w;
        __syncthreads();
#pragma unroll
        for (int kk = 0; kk < 16; kk++) {
            int cx = (kk >> 2) << 3;
            float ar[8], br[8];
            *(float4*)&ar[0] = *(const float4*)&As[kk][(tr << 3) ^ cx];
            *(float4*)&ar[4] = *(const float4*)&As[kk][((tr << 3) + 4) ^ cx];
            *(float4*)&br[0] = *(const float4*)&Bs[kk][(tc << 3) ^ cx];
            *(float4*)&br[4] = *(const float4*)&Bs[kk][((tc << 3) + 4) ^ cx];
#pragma unroll
            for (int i = 0; i < 8; i++)
#pragma unroll
                for (int j = 0; j < 8; j++) acc[i][j] += ar[i] * br[j];
        }
        __syncthreads();
    }

    // scatter-store into [qkv][b][h][n][d] scratch
    int o0 = bn * 128 + (tc << 3);
    int qkv = o0 >> 10;
    int hh = (o0 >> 6) & 15;
    int d0 = o0 & 63;
#pragma unroll
    for (int i = 0; i < 8; i++) {
        int m = bm * 128 + (tr << 3) + i;
        int b = m >> 11;
        int n = m & 2047;
        float* dst = g_qkv + ((((size_t)qkv * BATCH + b) * HEADS + hh) * NTOK + n) * DIM + d0;
        *(float4*)dst = make_float4(acc[i][0], acc[i][1], acc[i][2], acc[i][3]);
        *(float4*)(dst + 4) = make_float4(acc[i][4], acc[i][5], acc[i][6], acc[i][7]);
    }
}

// ---------------- fused attention ----------------
// One CTA per (b, h, 16-row tile). Full 16x2048 score tile in smem:
// QK^T once -> mask -> softmax (weights written to gmem) -> AV from same tile.
__global__ __launch_bounds__(256) void attn_kernel(const void* __restrict__ mask_raw,
                                                   float* __restrict__ att_out,
                                                   float* __restrict__ w_out) {
    extern __shared__ float sm[];
    float* S = sm;                            // 16*2048
    float* qs = S + 16 * NTOK;                // 16*68
    float* kv = qs + 16 * 68;                 // 256*64 (swizzled, K then V chunks)
    float* red = kv + 256 * 64;               // 4*16*64
    unsigned char* mj = (unsigned char*)(red + 4096);   // 2048
    float* mr = (float*)(mj + 2048);          // 16

    __shared__ int s_is32;

    int t = threadIdx.x;
    int b = blockIdx.z, h = blockIdx.y;
    int row0 = blockIdx.x << 4;

    // ---- detect mask dtype: int32 (all words 0/1) vs packed bytes ----
    if (t == 0) {
        const unsigned int* w = (const unsigned int*)mask_raw;
        int is32 = 1;
        for (int i = 0; i < 64; i++)
            if (w[i] > 1u) { is32 = 0; break; }
        s_is32 = is32;
    }
    __syncthreads();
    const int is32 = s_is32;
    const int* m32 = (const int*)mask_raw;
    const unsigned char* m8 = (const unsigned char*)mask_raw;

    const float* Qg = g_qkv + (((size_t)(0 * BATCH + b) * HEADS + h) * NTOK + row0) * DIM;
    const float* Kg = g_qkv + (((size_t)(1 * BATCH + b) * HEADS + h) * NTOK) * DIM;
    const float* Vg = g_qkv + (((size_t)(2 * BATCH + b) * HEADS + h) * NTOK) * DIM;

    // load Q tile (pre-scaled) + masks
    {
        int r = t >> 4;
        int d = (t & 15) << 2;
        float4 v = *(const float4*)(Qg + (size_t)r * DIM + d);
        v.x *= SCALE; v.y *= SCALE; v.z *= SCALE; v.w *= SCALE;
        *(float4*)&qs[r * 68 + d] = v;
    }
#pragma unroll
    for (int i = 0; i < 8; i++) {
        int j = t + (i << 8);
        mj[j] = is32 ? (unsigned char)(m32[(size_t)b * NTOK + j] != 0)
                     : m8[(size_t)b * NTOK + j];
    }
    if (t < 16) {
        int idx = (int)((size_t)b * NTOK) + row0 + t;
        int mv = is32 ? (m32[idx] != 0) : (m8[idx] != 0);
        mr[t] = mv ? 1.f : 0.f;
    }
    __syncthreads();

    // ---- S = Q K^T (scaled) with mask, tile held in smem ----
    {
        int rg = t >> 6;      // 4 row-groups of 4 rows
        int jj = t & 63;      // 64 j-threads, 4 cols each (stride 64)
        int swz = jj & 7;
        for (int jb = 0; jb < NTOK; jb += 256) {
            // stage K chunk [256][64], 16B-column XOR swizzle
#pragma unroll
            for (int i = 0; i < 16; i++) {
                int fidx = t + (i << 8);
                int j = fidx >> 4;
                int dq = fidx & 15;
                float4 vv = *(const float4*)(Kg + (size_t)(jb + j) * DIM + (dq << 2));
                *(float4*)&kv[(j << 6) + ((dq ^ (j & 7)) << 2)] = vv;
            }
            __syncthreads();
            float acc[4][4];
#pragma unroll
            for (int rr = 0; rr < 4; rr++)
#pragma unroll
                for (int c = 0; c < 4; c++) acc[rr][c] = 0.f;
#pragma unroll
            for (int d4 = 0; d4 < 16; d4++) {
                float4 q4[4];
#pragma unroll
                for (int rr = 0; rr < 4; rr++)
                    q4[rr] = *(const float4*)&qs[((rg << 2) + rr) * 68 + (d4 << 2)];
#pragma unroll
                for (int c = 0; c < 4; c++) {
                    float4 k4 = *(const float4*)&kv[((jj + (c << 6)) << 6) + ((d4 ^ swz) << 2)];
#pragma unroll
                    for (int rr = 0; rr < 4; rr++)
                        acc[rr][c] += q4[rr].x * k4.x + q4[rr].y * k4.y +
                                      q4[rr].z * k4.z + q4[rr].w * k4.w;
                }
            }
#pragma unroll
            for (int rr = 0; rr < 4; rr++) {
                int r = (rg << 2) + rr;
                bool rmask = (mr[r] != 0.f);
#pragma unroll
                for (int c = 0; c < 4; c++) {
                    int j = jb + jj + (c << 6);
                    S[r * NTOK + j] = (rmask || mj[j]) ? MASKV : acc[rr][c];
                }
            }
            __syncthreads();
        }
    }

    // ---- softmax per row (1 warp : 2 rows), write normalized weights ----
    {
        int w = t >> 5, lane = t & 31;
#pragma unroll
        for (int rr = 0; rr < 2; rr++) {
            int r = (w << 1) + rr;
            float* Srow = S + r * NTOK;
            float m = -1e30f;
            for (int j = lane; j < NTOK; j += 32) m = fmaxf(m, Srow[j]);
#pragma unroll
            for (int o = 16; o > 0; o >>= 1) m = fmaxf(m, __shfl_xor_sync(0xffffffffu, m, o));
            float sum = 0.f;
            for (int j = lane; j < NTOK; j += 32) {
                float e = __expf(Srow[j] - m);
                Srow[j] = e;
                sum += e;
            }
#pragma unroll
            for (int o = 16; o > 0; o >>= 1) sum += __shfl_xor_sync(0xffffffffu, sum, o);
            float inv = 1.f / sum;
            float* Wrow = w_out + ((size_t)(b * HEADS + h) * NTOK + row0 + r) * NTOK;
            for (int j = lane; j < NTOK; j += 32) {
                float val = Srow[j] * inv;
                Srow[j] = val;
                Wrow[j] = val;
            }
        }
    }
    __syncthreads();

    // ---- att = W @ V  (j split 4 ways across threads, reduced via smem) ----
    {
        int jp = t >> 6;            // j partition 0..3
        int rg = (t >> 4) & 3;      // 4 rows each
        int dg = t & 15;            // 4 d each
        float4 acc4[4];
#pragma unroll
        for (int rr = 0; rr < 4; rr++) acc4[rr] = make_float4(0.f, 0.f, 0.f, 0.f);
        for (int jb = 0; jb < NTOK; jb += 256) {
#pragma unroll
            for (int i = 0; i < 16; i++) {
                int fidx = t + (i << 8);
                int j = fidx >> 4;
                int dq = fidx & 15;
                float4 vv = *(const float4*)(Vg + (size_t)(jb + j) * DIM + (dq << 2));
                *(float4*)&kv[(j << 6) + ((dq ^ (j & 7)) << 2)] = vv;
            }
            __syncthreads();
            int jbase = jb + (jp << 6);
#pragma unroll
            for (int j4 = 0; j4 < 64; j4 += 4) {
                int j = jbase + j4;
                int jl = j - jb;
                float4 v4[4];
#pragma unroll
                for (int mq = 0; mq < 4; mq++) {
                    int jm = jl + mq;
                    v4[mq] = *(const float4*)&kv[(jm << 6) + ((dg ^ (jm & 7)) << 2)];
                }
#pragma unroll
                for (int rr = 0; rr < 4; rr++) {
                    float4 w4 = *(const float4*)&S[((rg << 2) + rr) * NTOK + j];
                    acc4[rr].x += w4.x * v4[0].x + w4.y * v4[1].x + w4.z * v4[2].x + w4.w * v4[3].x;
                    acc4[rr].y += w4.x * v4[0].y + w4.y * v4[1].y + w4.z * v4[2].y + w4.w * v4[3].y;
                    acc4[rr].z += w4.x * v4[0].z + w4.y * v4[1].z + w4.z * v4[2].z + w4.w * v4[3].z;
                    acc4[rr].w += w4.x * v4[0].w + w4.y * v4[1].w + w4.z * v4[2].w + w4.w * v4[3].w;
                }
            }
            __syncthreads();
        }
#pragma unroll
        for (int rr = 0; rr < 4; rr++)
            *(float4*)&red[((jp << 4) + (rg << 2) + rr) * 64 + (dg << 2)] = acc4[rr];
    }
    __syncthreads();
    {
        int r = t >> 4;
        int d = (t & 15) << 2;
        float4 s0 = *(const float4*)&red[(0 + r) * 64 + d];
        float4 s1 = *(const float4*)&red[(16 + r) * 64 + d];
        float4 s2 = *(const float4*)&red[(32 + r) * 64 + d];
        float4 s3 = *(const float4*)&red[(48 + r) * 64 + d];
        float4 o;
        o.x = s0.x + s1.x + s2.x + s3.x;
        o.y = s0.y + s1.y + s2.y + s3.y;
        o.z = s0.z + s1.z + s2.z + s3.z;
        o.w = s0.w + s1.w + s2.w + s3.w;
        float* dst = att_out + ((size_t)b * NTOK + row0 + r) * CHID + h * DIM + d;
        *(float4*)dst = o;
    }
}

#define ATT_SMEM ((16 * 2048 + 16 * 68 + 256 * 64 + 4096) * 4 + 2048 + 64)

extern "C" void kernel_launch(void* const* d_in, const int* in_sizes, int n_in,
                              void* d_out, int out_size) {
    (void)in_sizes; (void)n_in; (void)out_size;
    const float* X = (const float*)d_in[0];                 // [2,2048,1024] fp32
    const float* W = (const float*)d_in[1];                 // [3072,1024] fp32
    const void* mask = d_in[2];                             // [2,2048] bool or int32
    float* att = (float*)d_out;                             // [2,2048,1024]
    float* wts = (float*)d_out + (size_t)BATCH * NTOK * CHID;   // [2,16,2048,2048]

    cudaFuncSetAttribute(attn_kernel, cudaFuncAttributeMaxDynamicSharedMemorySize, ATT_SMEM);

    qkv_gemm_kernel<<<dim3(24, 32), 256>>>(X, W);
    attn_kernel<<<dim3(NTOK / 16, HEADS, BATCH), 256, ATT_SMEM>>>(mask, att, wts);
}

// round 3
// speedup vs baseline: 1.2232x; 1.2232x over previous
#include <cuda_runtime.h>
#include <mma.h>
#include <math.h>

using namespace nvcuda;

#define HEADS 16
#define DIM 64
#define NTOK 2048
#define CHID 1024
#define BATCH 2
#define SCALE 0.125f
#define MASKV -10000.0f

// scratch: [qkv][b][h][n][d]
__device__ float g_qkv[3UL * BATCH * HEADS * NTOK * DIM];

typedef wmma::fragment<wmma::matrix_a, 16, 16, 8, wmma::precision::tf32, wmma::row_major> AFrag;
typedef wmma::fragment<wmma::matrix_b, 16, 16, 8, wmma::precision::tf32, wmma::col_major> BFragCol;
typedef wmma::fragment<wmma::matrix_b, 16, 16, 8, wmma::precision::tf32, wmma::row_major> BFragRow;
typedef wmma::fragment<wmma::accumulator, 16, 16, 8, float> CFrag;

__device__ __forceinline__ float tf32r(float x) { return wmma::__float_to_tf32(x); }

// ---------------- QKV projection GEMM (tf32 tensor cores) ----------------
// C[m][o] = sum_k X[m][k] * W[o][k];  M=4096, N=3072, K=1024
__global__ __launch_bounds__(256) void qkv_gemm(const float* __restrict__ X,
                                                const float* __restrict__ Wt) {
    extern __shared__ float sm1[];
    float* As = sm1;              // [128][24]
    float* Bs = sm1 + 128 * 24;   // [128][24]
    float* Cs = sm1;              // alias for epilogue [128][72]

    int t = threadIdx.x;
    int bm = blockIdx.y, bn = blockIdx.x;
    int w = t >> 5;
    int wr = w >> 1;     // 0..3 : 32-row group
    int wc = w & 1;      // 0..1 : 64-col group
    int lrow = t >> 1;   // 0..127
    int lq = (t & 1) * 8;

    const float* Ag = X + (size_t)(bm * 128 + lrow) * 1024 + lq;
    const float* Bg = Wt + (size_t)(bn * 128 + lrow) * 1024 + lq;

    CFrag acc[2][4];
#pragma unroll
    for (int i = 0; i < 2; i++)
#pragma unroll
        for (int j = 0; j < 4; j++) wmma::fill_fragment(acc[i][j], 0.f);

    for (int k0 = 0; k0 < 1024; k0 += 16) {
        float4 a0 = *(const float4*)(Ag + k0);
        float4 a1 = *(const float4*)(Ag + k0 + 4);
        float4 b0 = *(const float4*)(Bg + k0);
        float4 b1 = *(const float4*)(Bg + k0 + 4);
        float* ap = &As[lrow * 24 + lq];
        float* bp = &Bs[lrow * 24 + lq];
        ap[0] = tf32r(a0.x); ap[1] = tf32r(a0.y); ap[2] = tf32r(a0.z); ap[3] = tf32r(a0.w);
        ap[4] = tf32r(a1.x); ap[5] = tf32r(a1.y); ap[6] = tf32r(a1.z); ap[7] = tf32r(a1.w);
        bp[0] = tf32r(b0.x); bp[1] = tf32r(b0.y); bp[2] = tf32r(b0.z); bp[3] = tf32r(b0.w);
        bp[4] = tf32r(b1.x); bp[5] = tf32r(b1.y); bp[6] = tf32r(b1.z); bp[7] = tf32r(b1.w);
        __syncthreads();
#pragma unroll
        for (int ks = 0; ks < 2; ks++) {
            AFrag af[2];
            BFragCol bf[4];
#pragma unroll
            for (int i = 0; i < 2; i++)
                wmma::load_matrix_sync(af[i], &As[(wr * 32 + i * 16) * 24 + ks * 8], 24);
#pragma unroll
            for (int j = 0; j < 4; j++)
                wmma::load_matrix_sync(bf[j], &Bs[(wc * 64 + j * 16) * 24 + ks * 8], 24);
#pragma unroll
            for (int i = 0; i < 2; i++)
#pragma unroll
                for (int j = 0; j < 4; j++)
                    wmma::mma_sync(acc[i][j], af[i], bf[j], acc[i][j]);
        }
        __syncthreads();
    }

    // epilogue: stage 64-col half in smem, scatter to g_qkv layout
#pragma unroll
    for (int hf = 0; hf < 2; hf++) {
        if (wc == hf) {
#pragma unroll
            for (int i = 0; i < 2; i++)
#pragma unroll
                for (int j = 0; j < 4; j++)
                    wmma::store_matrix_sync(&Cs[(wr * 32 + i * 16) * 72 + j * 16],
                                            acc[i][j], 72, wmma::mem_row_major);
        }
        __syncthreads();
        int colbase = bn * 128 + hf * 64;
        int qkv = colbase >> 10;
        int hh = (colbase >> 6) & 15;
#pragma unroll
        for (int i = 0; i < 8; i++) {
            int fi = t + (i << 8);       // 0..2047 float4 units
            int row = fi >> 4;
            int c4 = fi & 15;
            int m = bm * 128 + row;
            int b = m >> 11, n = m & 2047;
            float4 v = *(const float4*)&Cs[row * 72 + c4 * 4];
            float* dst = g_qkv + ((((size_t)qkv * BATCH + b) * HEADS + hh) * NTOK + n) * DIM + c4 * 4;
            *(float4*)dst = v;
        }
        __syncthreads();
    }
}

// ---------------- fused attention (tf32 tensor cores) ----------------
// One CTA per (b, h, 16 q-rows). S[16][2048] held in smem.
__global__ __launch_bounds__(256) void attn_kernel(const void* __restrict__ mask_raw,
                                                   float* __restrict__ att_out,
                                                   float* __restrict__ w_out) {
    extern __shared__ float sm[];
    float* S = sm;                         // [16][2048]
    float* qs = S + 16 * NTOK;             // [16][72]
    float* kv = qs + 16 * 72;              // [256][72]  (K/V staging, also AV reduce)
    unsigned char* mj = (unsigned char*)(kv + 256 * 72);   // 2048 bytes
    float* mr = (float*)(mj + 2048);       // 16 floats

    __shared__ int s_is32;

    int t = threadIdx.x;
    int w = t >> 5, lane = t & 31;
    int b = blockIdx.z, h = blockIdx.y;
    int row0 = blockIdx.x << 4;

    if (t == 0) {
        const unsigned int* mw = (const unsigned int*)mask_raw;
        int is32 = 1;
        for (int i = 0; i < 64; i++)
            if (mw[i] > 1u) { is32 = 0; break; }
        s_is32 = is32;
    }
    __syncthreads();
    const int is32 = s_is32;
    const int* m32 = (const int*)mask_raw;
    const unsigned char* m8 = (const unsigned char*)mask_raw;

    const float* Qg = g_qkv + (((size_t)(0 * BATCH + b) * HEADS + h) * NTOK + row0) * DIM;
    const float* Kg = g_qkv + (((size_t)(1 * BATCH + b) * HEADS + h) * NTOK) * DIM;
    const float* Vg = g_qkv + (((size_t)(2 * BATCH + b) * HEADS + h) * NTOK) * DIM;

    // stage Q (scaled + tf32) and masks
    {
        int r = t >> 4;
        int d = (t & 15) << 2;
        float4 v = *(const float4*)(Qg + (size_t)r * DIM + d);
        float* qp = &qs[r * 72 + d];
        qp[0] = tf32r(v.x * SCALE);
        qp[1] = tf32r(v.y * SCALE);
        qp[2] = tf32r(v.z * SCALE);
        qp[3] = tf32r(v.w * SCALE);
    }
#pragma unroll
    for (int i = 0; i < 8; i++) {
        int j = t + (i << 8);
        mj[j] = is32 ? (unsigned char)(m32[(size_t)b * NTOK + j] != 0)
                     : m8[(size_t)b * NTOK + j];
    }
    if (t < 16) {
        int idx = b * NTOK + row0 + t;
        int mv = is32 ? (m32[idx] != 0) : (m8[idx] != 0);
        mr[t] = mv ? 1.f : 0.f;
    }
    __syncthreads();

    // ---- S = Q K^T ----
    {
        AFrag aq[8];
#pragma unroll
        for (int ks = 0; ks < 8; ks++)
            wmma::load_matrix_sync(aq[ks], &qs[ks * 8], 72);

        for (int cb = 0; cb < 8; cb++) {
            // stage K chunk [256][64] (tf32), ld 72
#pragma unroll
            for (int i = 0; i < 16; i++) {
                int fi = t + (i << 8);
                int j = fi >> 4;
                int dq = (fi & 15) << 2;
                float4 v = *(const float4*)(Kg + (size_t)(cb * 256 + j) * DIM + dq);
                float* p = &kv[j * 72 + dq];
                p[0] = tf32r(v.x); p[1] = tf32r(v.y); p[2] = tf32r(v.z); p[3] = tf32r(v.w);
            }
            __syncthreads();

            CFrag acc0, acc1;
            wmma::fill_fragment(acc0, 0.f);
            wmma::fill_fragment(acc1, 0.f);
            int c0 = w * 32;
#pragma unroll
            for (int ks = 0; ks < 8; ks++) {
                BFragCol b0, b1;
                wmma::load_matrix_sync(b0, &kv[(c0 + 0) * 72 + ks * 8], 72);
                wmma::load_matrix_sync(b1, &kv[(c0 + 16) * 72 + ks * 8], 72);
                wmma::mma_sync(acc0, aq[ks], b0, acc0);
                wmma::mma_sync(acc1, aq[ks], b1, acc1);
            }
            wmma::store_matrix_sync(&S[cb * 256 + c0], acc0, NTOK, wmma::mem_row_major);
            wmma::store_matrix_sync(&S[cb * 256 + c0 + 16], acc1, NTOK, wmma::mem_row_major);
            __syncthreads();
        }
    }

    // ---- mask + softmax; write exact weights, keep tf32 weights in S ----
    {
#pragma unroll
        for (int rr = 0; rr < 2; rr++) {
            int r = (w << 1) + rr;
            float* Srow = S + r * NTOK;
            bool rm = (mr[r] != 0.f);
            float m = -1e30f;
            for (int j = lane; j < NTOK; j += 32) {
                float v = (rm || mj[j]) ? MASKV : Srow[j];
                Srow[j] = v;
                m = fmaxf(m, v);
            }
#pragma unroll
            for (int o = 16; o > 0; o >>= 1) m = fmaxf(m, __shfl_xor_sync(0xffffffffu, m, o));
            float sum = 0.f;
            for (int j = lane; j < NTOK; j += 32) {
                float e = __expf(Srow[j] - m);
                Srow[j] = e;
                sum += e;
            }
#pragma unroll
            for (int o = 16; o > 0; o >>= 1) sum += __shfl_xor_sync(0xffffffffu, sum, o);
            float inv = 1.f / sum;
            float* Wrow = w_out + ((size_t)(b * HEADS + h) * NTOK + row0 + r) * NTOK;
            for (int j = lane; j < NTOK; j += 32) {
                float val = Srow[j] * inv;
                Wrow[j] = val;              // exact fp32 weights out
                Srow[j] = tf32r(val);       // tf32-rounded copy for AV
            }
        }
    }
    __syncthreads();

    // ---- att = W @ V  (k split across warps, tensor cores, smem reduce) ----
    {
        CFrag acc[4];
#pragma unroll
        for (int dt = 0; dt < 4; dt++) wmma::fill_fragment(acc[dt], 0.f);

        for (int cb = 0; cb < 8; cb++) {
            // stage V chunk [256][64] (tf32)
#pragma unroll
            for (int i = 0; i < 16; i++) {
                int fi = t + (i << 8);
                int j = fi >> 4;
                int dq = (fi & 15) << 2;
                float4 v = *(const float4*)(Vg + (size_t)(cb * 256 + j) * DIM + dq);
                float* p = &kv[j * 72 + dq];
                p[0] = tf32r(v.x); p[1] = tf32r(v.y); p[2] = tf32r(v.z); p[3] = tf32r(v.w);
            }
            __syncthreads();

            int jl0 = w * 32;
#pragma unroll
            for (int ks = 0; ks < 4; ks++) {
                AFrag aw;
                wmma::load_matrix_sync(aw, &S[cb * 256 + jl0 + ks * 8], NTOK);
#pragma unroll
                for (int dt = 0; dt < 4; dt++) {
                    BFragRow bv;
                    wmma::load_matrix_sync(bv, &kv[(jl0 + ks * 8) * 72 + dt * 16], 72);
                    wmma::mma_sync(acc[dt], aw, bv, acc[dt]);
                }
            }
            __syncthreads();
        }

        // partials -> smem (alias kv), reduce across warps
        float* red = kv;   // [8][16][72]
#pragma unroll
        for (int dt = 0; dt < 4; dt++)
            wmma::store_matrix_sync(&red[w * 16 * 72 + dt * 16], acc[dt], 72, wmma::mem_row_major);
        __syncthreads();

        int r = t >> 4;
        int d = (t & 15) << 2;
        float4 o = make_float4(0.f, 0.f, 0.f, 0.f);
#pragma unroll
        for (int ww = 0; ww < 8; ww++) {
            float4 p = *(const float4*)&red[ww * 16 * 72 + r * 72 + d];
            o.x += p.x; o.y += p.y; o.z += p.z; o.w += p.w;
        }
        float* dst = att_out + ((size_t)b * NTOK + row0 + r) * CHID + h * DIM + d;
        *(float4*)dst = o;
    }
}

#define GEMM_SMEM (128 * 72 * 4)
#define ATT_SMEM ((16 * 2048 + 16 * 72 + 256 * 72) * 4 + 2048 + 64)

extern "C" void kernel_launch(void* const* d_in, const int* in_sizes, int n_in,
                              void* d_out, int out_size) {
    (void)in_sizes; (void)n_in; (void)out_size;
    const float* X = (const float*)d_in[0];
    const float* W = (const float*)d_in[1];
    const void* mask = d_in[2];
    float* att = (float*)d_out;
    float* wts = (float*)d_out + (size_t)BATCH * NTOK * CHID;

    cudaFuncSetAttribute(attn_kernel, cudaFuncAttributeMaxDynamicSharedMemorySize, ATT_SMEM);

    qkv_gemm<<<dim3(24, 32), 256, GEMM_SMEM>>>(X, W);
    attn_kernel<<<dim3(NTOK / 16, HEADS, BATCH), 256, ATT_SMEM>>>(mask, att, wts);
}

// round 4
// speedup vs baseline: 1.3871x; 1.1340x over previous
#include <cuda_runtime.h>
#include <mma.h>
#include <math.h>

using namespace nvcuda;

#define HEADS 16
#define DIM 64
#define NTOK 2048
#define CHID 1024
#define BATCH 2
#define SCALE 0.125f
#define MASKV -10000.0f
#define SLD 2056   // S row stride (2048 + 8 pad)

__device__ float g_qkv[3UL * BATCH * HEADS * NTOK * DIM];

typedef wmma::fragment<wmma::matrix_a, 16, 16, 8, wmma::precision::tf32, wmma::row_major> AFrag;
typedef wmma::fragment<wmma::matrix_b, 16, 16, 8, wmma::precision::tf32, wmma::col_major> BFragCol;
typedef wmma::fragment<wmma::matrix_b, 16, 16, 8, wmma::precision::tf32, wmma::row_major> BFragRow;
typedef wmma::fragment<wmma::accumulator, 16, 16, 8, float> CFrag;

__device__ __forceinline__ float tf32r(float x) { return wmma::__float_to_tf32(x); }
__device__ __forceinline__ float4 tf4(float4 v) {
    v.x = tf32r(v.x); v.y = tf32r(v.y); v.z = tf32r(v.z); v.w = tf32r(v.w);
    return v;
}
__device__ __forceinline__ void cp16(void* s, const void* g) {
    unsigned sa = (unsigned)__cvta_generic_to_shared(s);
    asm volatile("cp.async.cg.shared.global [%0], [%1], 16;" :: "r"(sa), "l"(g));
}
#define CP_COMMIT() asm volatile("cp.async.commit_group;")
#define CP_WAIT(n) asm volatile("cp.async.wait_group %0;" :: "n"(n))

// ---------------- QKV projection GEMM (tf32 tensor cores) ----------------
__global__ __launch_bounds__(256) void qkv_gemm(const float* __restrict__ X,
                                                const float* __restrict__ Wt) {
    extern __shared__ float sm1[];
    float* As = sm1;              // [128][24]
    float* Bs = sm1 + 128 * 24;   // [128][24]
    float* Cs = sm1;              // epilogue alias [128][72]

    int t = threadIdx.x;
    int bm = blockIdx.y, bn = blockIdx.x;
    int w = t >> 5;
    int wr = w >> 1, wc = w & 1;
    int lrow = t >> 1;
    int lq = (t & 1) * 8;

    const float* Ag = X + (size_t)(bm * 128 + lrow) * 1024 + lq;
    const float* Bg = Wt + (size_t)(bn * 128 + lrow) * 1024 + lq;

    CFrag acc[2][4];
#pragma unroll
    for (int i = 0; i < 2; i++)
#pragma unroll
        for (int j = 0; j < 4; j++) wmma::fill_fragment(acc[i][j], 0.f);

    float4 a0 = *(const float4*)(Ag);
    float4 a1 = *(const float4*)(Ag + 4);
    float4 b0 = *(const float4*)(Bg);
    float4 b1 = *(const float4*)(Bg + 4);

    for (int k0 = 0; k0 < 1024; k0 += 16) {
        float* ap = &As[lrow * 24 + lq];
        float* bp = &Bs[lrow * 24 + lq];
        *(float4*)ap = tf4(a0);
        *(float4*)(ap + 4) = tf4(a1);
        *(float4*)bp = tf4(b0);
        *(float4*)(bp + 4) = tf4(b1);
        __syncthreads();
        if (k0 + 16 < 1024) {
            a0 = *(const float4*)(Ag + k0 + 16);
            a1 = *(const float4*)(Ag + k0 + 20);
            b0 = *(const float4*)(Bg + k0 + 16);
            b1 = *(const float4*)(Bg + k0 + 20);
        }
#pragma unroll
        for (int ks = 0; ks < 2; ks++) {
            AFrag af[2];
            BFragCol bf[4];
#pragma unroll
            for (int i = 0; i < 2; i++)
                wmma::load_matrix_sync(af[i], &As[(wr * 32 + i * 16) * 24 + ks * 8], 24);
#pragma unroll
            for (int j = 0; j < 4; j++)
                wmma::load_matrix_sync(bf[j], &Bs[(wc * 64 + j * 16) * 24 + ks * 8], 24);
#pragma unroll
            for (int i = 0; i < 2; i++)
#pragma unroll
                for (int j = 0; j < 4; j++)
                    wmma::mma_sync(acc[i][j], af[i], bf[j], acc[i][j]);
        }
        __syncthreads();
    }

    // epilogue: round to tf32, scatter to g_qkv layout
#pragma unroll
    for (int hf = 0; hf < 2; hf++) {
        if (wc == hf) {
#pragma unroll
            for (int i = 0; i < 2; i++)
#pragma unroll
                for (int j = 0; j < 4; j++)
                    wmma::store_matrix_sync(&Cs[(wr * 32 + i * 16) * 72 + j * 16],
                                            acc[i][j], 72, wmma::mem_row_major);
        }
        __syncthreads();
        int colbase = bn * 128 + hf * 64;
        int qkv = colbase >> 10;
        int hh = (colbase >> 6) & 15;
#pragma unroll
        for (int i = 0; i < 8; i++) {
            int fi = t + (i << 8);
            int row = fi >> 4;
            int c4 = fi & 15;
            int m = bm * 128 + row;
            int b = m >> 11, n = m & 2047;
            float4 v = tf4(*(const float4*)&Cs[row * 72 + c4 * 4]);
            float* dst = g_qkv + ((((size_t)qkv * BATCH + b) * HEADS + hh) * NTOK + n) * DIM + c4 * 4;
            *(float4*)dst = v;
        }
        __syncthreads();
    }
}

// ---------------- fused attention (tf32, cp.async double-buffered) ----------------
__global__ __launch_bounds__(256) void attn_kernel(const void* __restrict__ mask_raw,
                                                   float* __restrict__ att_out,
                                                   float* __restrict__ w_out) {
    extern __shared__ float sm[];
    float* S = sm;                          // [16][SLD]
    float* qs = S + 16 * SLD;               // [16][72]
    float* kv = qs + 16 * 72;               // 2 x [128][72]
    unsigned char* mj = (unsigned char*)(kv + 2 * 128 * 72);  // 2048
    float* mr = (float*)(mj + 2048);        // 16

    __shared__ int s_is32;

    int t = threadIdx.x;
    int w = t >> 5, lane = t & 31;
    int b = blockIdx.z, h = blockIdx.y;
    int row0 = blockIdx.x << 4;

    const float* Qg = g_qkv + (((size_t)(0 * BATCH + b) * HEADS + h) * NTOK + row0) * DIM;
    const float* Kg = g_qkv + (((size_t)(1 * BATCH + b) * HEADS + h) * NTOK) * DIM;
    const float* Vg = g_qkv + (((size_t)(2 * BATCH + b) * HEADS + h) * NTOK) * DIM;

    // prefetch Q tile + K chunk 0 (group 0)
    {
        int r = t >> 4;
        int dq = (t & 15) << 2;
        cp16(&qs[r * 72 + dq], Qg + (size_t)r * DIM + dq);
#pragma unroll
        for (int i = 0; i < 8; i++) {
            int fi = t + (i << 8);
            int j = fi >> 4;
            int d2 = (fi & 15) << 2;
            cp16(&kv[j * 72 + d2], Kg + (size_t)j * DIM + d2);
        }
        CP_COMMIT();
    }

    // mask dtype detect + stage masks
    if (t == 0) {
        const unsigned int* mw = (const unsigned int*)mask_raw;
        int is32 = 1;
        for (int i = 0; i < 64; i++)
            if (mw[i] > 1u) { is32 = 0; break; }
        s_is32 = is32;
    }
    __syncthreads();
    {
        const int is32 = s_is32;
        const int* m32 = (const int*)mask_raw;
        const unsigned char* m8 = (const unsigned char*)mask_raw;
#pragma unroll
        for (int i = 0; i < 8; i++) {
            int j = t + (i << 8);
            mj[j] = is32 ? (unsigned char)(m32[(size_t)b * NTOK + j] != 0)
                         : m8[(size_t)b * NTOK + j];
        }
        if (t < 16) {
            int idx = b * NTOK + row0 + t;
            int mv = is32 ? (m32[idx] != 0) : (m8[idx] != 0);
            mr[t] = mv ? 1.f : 0.f;
        }
    }

    // ---- S = Q K^T, 16 chunks of 128 cols, double buffered ----
    {
        AFrag aq[8];
        for (int cb = 0; cb < 16; cb++) {
            if (cb + 1 < 16) {
                float* dst = kv + ((cb + 1) & 1) * (128 * 72);
#pragma unroll
                for (int i = 0; i < 8; i++) {
                    int fi = t + (i << 8);
                    int j = fi >> 4;
                    int d2 = (fi & 15) << 2;
                    cp16(&dst[j * 72 + d2], Kg + (size_t)((cb + 1) * 128 + j) * DIM + d2);
                }
                CP_COMMIT();
                CP_WAIT(1);
            } else {
                CP_WAIT(0);
            }
            __syncthreads();
            float* buf = kv + (cb & 1) * (128 * 72);
            if (cb == 0) {
#pragma unroll
                for (int ks = 0; ks < 8; ks++)
                    wmma::load_matrix_sync(aq[ks], &qs[ks * 8], 72);
            }
            CFrag acc;
            wmma::fill_fragment(acc, 0.f);
            int c0 = w * 16;
#pragma unroll
            for (int ks = 0; ks < 8; ks++) {
                BFragCol bf;
                wmma::load_matrix_sync(bf, &buf[c0 * 72 + ks * 8], 72);
                wmma::mma_sync(acc, aq[ks], bf, acc);
            }
            wmma::store_matrix_sync(&S[cb * 128 + c0], acc, SLD, wmma::mem_row_major);
            __syncthreads();
        }
    }

    // prefetch V chunk 0 (hidden behind softmax)
    {
#pragma unroll
        for (int i = 0; i < 8; i++) {
            int fi = t + (i << 8);
            int j = fi >> 4;
            int d2 = (fi & 15) << 2;
            cp16(&kv[j * 72 + d2], Vg + (size_t)j * DIM + d2);
        }
        CP_COMMIT();
    }

    // ---- mask + scale + softmax; exact weights to gmem, tf32 weights in S ----
    {
#pragma unroll
        for (int rr = 0; rr < 2; rr++) {
            int r = (w << 1) + rr;
            float* Srow = S + r * SLD;
            bool rm = (mr[r] != 0.f);
            float m = -1e30f;
            for (int j = lane; j < NTOK; j += 32) {
                float v = (rm || mj[j]) ? MASKV : Srow[j] * SCALE;
                Srow[j] = v;
                m = fmaxf(m, v);
            }
#pragma unroll
            for (int o = 16; o > 0; o >>= 1) m = fmaxf(m, __shfl_xor_sync(0xffffffffu, m, o));
            float sum = 0.f;
            for (int j = lane; j < NTOK; j += 32) {
                float e = __expf(Srow[j] - m);
                Srow[j] = e;
                sum += e;
            }
#pragma unroll
            for (int o = 16; o > 0; o >>= 1) sum += __shfl_xor_sync(0xffffffffu, sum, o);
            float inv = 1.f / sum;
            float* Wrow = w_out + ((size_t)(b * HEADS + h) * NTOK + row0 + r) * NTOK;
            for (int j = lane; j < NTOK; j += 32) {
                float val = Srow[j] * inv;
                Wrow[j] = val;
                Srow[j] = tf32r(val);
            }
        }
    }
    __syncthreads();

    // ---- att = W @ V, 16 chunks, k-split across warps, double buffered ----
    {
        CFrag acc[4];
#pragma unroll
        for (int dt = 0; dt < 4; dt++) wmma::fill_fragment(acc[dt], 0.f);

        for (int cb = 0; cb < 16; cb++) {
            if (cb + 1 < 16) {
                float* dst = kv + ((cb + 1) & 1) * (128 * 72);
#pragma unroll
                for (int i = 0; i < 8; i++) {
                    int fi = t + (i << 8);
                    int j = fi >> 4;
                    int d2 = (fi & 15) << 2;
                    cp16(&dst[j * 72 + d2], Vg + (size_t)((cb + 1) * 128 + j) * DIM + d2);
                }
                CP_COMMIT();
                CP_WAIT(1);
            } else {
                CP_WAIT(0);
            }
            __syncthreads();
            float* buf = kv + (cb & 1) * (128 * 72);
            int jl0 = w * 16;
#pragma unroll
            for (int ks2 = 0; ks2 < 2; ks2++) {
                AFrag aw;
                wmma::load_matrix_sync(aw, &S[cb * 128 + jl0 + ks2 * 8], SLD);
#pragma unroll
                for (int dt = 0; dt < 4; dt++) {
                    BFragRow bv;
                    wmma::load_matrix_sync(bv, &buf[(jl0 + ks2 * 8) * 72 + dt * 16], 72);
                    wmma::mma_sync(acc[dt], aw, bv, acc[dt]);
                }
            }
            __syncthreads();
        }

        // reduce 8 warps' partials via smem (alias kv)
        float* red = kv;   // [8][16][72]
#pragma unroll
        for (int dt = 0; dt < 4; dt++)
            wmma::store_matrix_sync(&red[w * 16 * 72 + dt * 16], acc[dt], 72, wmma::mem_row_major);
        __syncthreads();

        int r = t >> 4;
        int d = (t & 15) << 2;
        float4 o = make_float4(0.f, 0.f, 0.f, 0.f);
#pragma unroll
        for (int ww = 0; ww < 8; ww++) {
            float4 p = *(const float4*)&red[ww * 16 * 72 + r * 72 + d];
            o.x += p.x; o.y += p.y; o.z += p.z; o.w += p.w;
        }
        float* dst = att_out + ((size_t)b * NTOK + row0 + r) * CHID + h * DIM + d;
        *(float4*)dst = o;
    }
}

#define GEMM_SMEM (128 * 72 * 4)
#define ATT_SMEM ((16 * SLD + 16 * 72 + 2 * 128 * 72) * 4 + 2048 + 64)

extern "C" void kernel_launch(void* const* d_in, const int* in_sizes, int n_in,
                              void* d_out, int out_size) {
    (void)in_sizes; (void)n_in; (void)out_size;
    const float* X = (const float*)d_in[0];
    const float* W = (const float*)d_in[1];
    const void* mask = d_in[2];
    float* att = (float*)d_out;
    float* wts = (float*)d_out + (size_t)BATCH * NTOK * CHID;

    cudaFuncSetAttribute(attn_kernel, cudaFuncAttributeMaxDynamicSharedMemorySize, ATT_SMEM);

    qkv_gemm<<<dim3(24, 32), 256, GEMM_SMEM>>>(X, W);
    attn_kernel<<<dim3(NTOK / 16, HEADS, BATCH), 256, ATT_SMEM>>>(mask, att, wts);
}

// round 7
// speedup vs baseline: 1.4901x; 1.0743x over previous
#include <cuda_runtime.h>
#include <mma.h>
#include <math.h>

using namespace nvcuda;

#define HEADS 16
#define DIM 64
#define NTOK 2048
#define CHID 1024
#define BATCH 2
#define SCALE 0.125f

__device__ float g_qkv[3UL * BATCH * HEADS * NTOK * DIM];
__device__ float g_inv[(size_t)BATCH * HEADS * NTOK];

typedef wmma::fragment<wmma::matrix_a, 16, 16, 8, wmma::precision::tf32, wmma::row_major> AFrag;
typedef wmma::fragment<wmma::matrix_b, 16, 16, 8, wmma::precision::tf32, wmma::col_major> BFragCol;
typedef wmma::fragment<wmma::matrix_b, 16, 16, 8, wmma::precision::tf32, wmma::row_major> BFragRow;
typedef wmma::fragment<wmma::accumulator, 16, 16, 8, float> CFrag;

__device__ __forceinline__ float tf32r(float x) { return wmma::__float_to_tf32(x); }
__device__ __forceinline__ float4 tf4(float4 v) {
    v.x = tf32r(v.x); v.y = tf32r(v.y); v.z = tf32r(v.z); v.w = tf32r(v.w);
    return v;
}
__device__ __forceinline__ void cp16(void* s, const void* g) {
    unsigned sa = (unsigned)__cvta_generic_to_shared(s);
    asm volatile("cp.async.cg.shared.global [%0], [%1], 16;" :: "r"(sa), "l"(g));
}
#define CP_COMMIT() asm volatile("cp.async.commit_group;")
#define CP_WAIT(n) asm volatile("cp.async.wait_group %0;" :: "n"(n))

// ---------------- QKV projection GEMM (tf32) ----------------
__global__ __launch_bounds__(256) void qkv_gemm(const float* __restrict__ X,
                                                const float* __restrict__ Wt) {
    extern __shared__ float sm1[];
    float* As = sm1;
    float* Bs = sm1 + 128 * 24;
    float* Cs = sm1;

    int t = threadIdx.x;
    int bm = blockIdx.y, bn = blockIdx.x;
    int w = t >> 5;
    int wr = w >> 1, wc = w & 1;
    int lrow = t >> 1;
    int lq = (t & 1) * 8;

    const float* Ag = X + (size_t)(bm * 128 + lrow) * 1024 + lq;
    const float* Bg = Wt + (size_t)(bn * 128 + lrow) * 1024 + lq;

    CFrag acc[2][4];
#pragma unroll
    for (int i = 0; i < 2; i++)
#pragma unroll
        for (int j = 0; j < 4; j++) wmma::fill_fragment(acc[i][j], 0.f);

    float4 a0 = *(const float4*)(Ag);
    float4 a1 = *(const float4*)(Ag + 4);
    float4 b0 = *(const float4*)(Bg);
    float4 b1 = *(const float4*)(Bg + 4);

    for (int k0 = 0; k0 < 1024; k0 += 16) {
        float* ap = &As[lrow * 24 + lq];
        float* bp = &Bs[lrow * 24 + lq];
        *(float4*)ap = tf4(a0);
        *(float4*)(ap + 4) = tf4(a1);
        *(float4*)bp = tf4(b0);
        *(float4*)(bp + 4) = tf4(b1);
        __syncthreads();
        if (k0 + 16 < 1024) {
            a0 = *(const float4*)(Ag + k0 + 16);
            a1 = *(const float4*)(Ag + k0 + 20);
            b0 = *(const float4*)(Bg + k0 + 16);
            b1 = *(const float4*)(Bg + k0 + 20);
        }
#pragma unroll
        for (int ks = 0; ks < 2; ks++) {
            AFrag af[2];
            BFragCol bf[4];
#pragma unroll
            for (int i = 0; i < 2; i++)
                wmma::load_matrix_sync(af[i], &As[(wr * 32 + i * 16) * 24 + ks * 8], 24);
#pragma unroll
            for (int j = 0; j < 4; j++)
                wmma::load_matrix_sync(bf[j], &Bs[(wc * 64 + j * 16) * 24 + ks * 8], 24);
#pragma unroll
            for (int i = 0; i < 2; i++)
#pragma unroll
                for (int j = 0; j < 4; j++)
                    wmma::mma_sync(acc[i][j], af[i], bf[j], acc[i][j]);
        }
        __syncthreads();
    }

#pragma unroll
    for (int hf = 0; hf < 2; hf++) {
        if (wc == hf) {
#pragma unroll
            for (int i = 0; i < 2; i++)
#pragma unroll
                for (int j = 0; j < 4; j++)
                    wmma::store_matrix_sync(&Cs[(wr * 32 + i * 16) * 72 + j * 16],
                                            acc[i][j], 72, wmma::mem_row_major);
        }
        __syncthreads();
        int colbase = bn * 128 + hf * 64;
        int qkv = colbase >> 10;
        int hh = (colbase >> 6) & 15;
#pragma unroll
        for (int i = 0; i < 8; i++) {
            int fi = t + (i << 8);
            int row = fi >> 4;
            int c4 = fi & 15;
            int m = bm * 128 + row;
            int b = m >> 11, n = m & 2047;
            float4 v = tf4(*(const float4*)&Cs[row * 72 + c4 * 4]);
            float* dst = g_qkv + ((((size_t)qkv * BATCH + b) * HEADS + hh) * NTOK + n) * DIM + c4 * 4;
            *(float4*)dst = v;
        }
        __syncthreads();
    }
}

// ---------------- attention: 128-row Q tiles, flash-style (no max) ----------------
__global__ __launch_bounds__(256) void attn_scores(const void* __restrict__ mask_raw,
                                                   float* __restrict__ att_out,
                                                   float* __restrict__ w_out) {
    extern __shared__ float sm[];
    float* qs = sm;                     // [128][72]
    float* kb = qs + 128 * 72;          // 2 x [128][72]
    float* sc = kb + 2 * 128 * 72;      // [128][132]
    float* rowsum = sc + 128 * 132;     // [128]
    unsigned char* mj = (unsigned char*)(rowsum + 128);  // 2048
    unsigned char* mr = mj + 2048;      // 128

    __shared__ int s_is32;

    int t = threadIdx.x;
    int w = t >> 5;
    int b = blockIdx.z, h = blockIdx.y;
    int row0 = blockIdx.x << 7;

    const float* Qg = g_qkv + (((size_t)(0 * BATCH + b) * HEADS + h) * NTOK + row0) * DIM;
    const float* Kg = g_qkv + (((size_t)(1 * BATCH + b) * HEADS + h) * NTOK) * DIM;
    const float* Vg = g_qkv + (((size_t)(2 * BATCH + b) * HEADS + h) * NTOK) * DIM;
    float* Wt = w_out + ((size_t)(b * HEADS + h) * NTOK + row0) * NTOK;

    // stage Q + K chunk 0 (cp.async group A)
#pragma unroll
    for (int i = 0; i < 8; i++) {
        int fi = t + (i << 8);
        int r = fi >> 4;
        int d4 = (fi & 15) << 2;
        cp16(&qs[r * 72 + d4], Qg + (size_t)r * DIM + d4);
        cp16(&kb[r * 72 + d4], Kg + (size_t)r * DIM + d4);
    }
    CP_COMMIT();

    if (t == 0) {
        const unsigned int* mw = (const unsigned int*)mask_raw;
        int is32 = 1;
        for (int i = 0; i < 64; i++)
            if (mw[i] > 1u) { is32 = 0; break; }
        s_is32 = is32;
    }
    __syncthreads();
    {
        const int is32 = s_is32;
        const int* m32 = (const int*)mask_raw;
        const unsigned char* m8 = (const unsigned char*)mask_raw;
#pragma unroll
        for (int i = 0; i < 8; i++) {
            int j = t + (i << 8);
            mj[j] = is32 ? (unsigned char)(m32[(size_t)b * NTOK + j] != 0)
                         : m8[(size_t)b * NTOK + j];
        }
        // row mask read DIRECTLY from global (mj written by other threads — no
        // barrier yet; reading mj here was the R5/R6 race)
        if (t < 128) {
            int idx = b * NTOK + row0 + t;
            int mv = is32 ? (m32[idx] != 0) : (m8[idx] != 0);
            mr[t] = (unsigned char)mv;
            rowsum[t] = 0.f;
        }
    }
    __syncthreads();

    // ---------- Phase A: e = masked exp(QK^T * SCALE) -> w_out + rowsum ----------
    {
        AFrag aq[8];

        for (int cb = 0; cb < 16; cb++) {
            if (cb + 1 < 16) {
                float* dst = kb + ((cb + 1) & 1) * (128 * 72);
#pragma unroll
                for (int i = 0; i < 8; i++) {
                    int fi = t + (i << 8);
                    int r = fi >> 4;
                    int d4 = (fi & 15) << 2;
                    cp16(&dst[r * 72 + d4], Kg + (size_t)((cb + 1) * 128 + r) * DIM + d4);
                }
                CP_COMMIT();
                CP_WAIT(1);
            } else {
                CP_WAIT(0);
            }
            __syncthreads();
            float* buf = kb + (cb & 1) * (128 * 72);

            if (cb == 0) {
#pragma unroll
                for (int k = 0; k < 8; k++)
                    wmma::load_matrix_sync(aq[k], &qs[(w * 16) * 72 + k * 8], 72);
            }

#pragma unroll
            for (int c = 0; c < 8; c++) {
                CFrag acc;
                wmma::fill_fragment(acc, 0.f);
#pragma unroll
                for (int k = 0; k < 8; k++) {
                    BFragCol bf;
                    wmma::load_matrix_sync(bf, &buf[(c * 16) * 72 + k * 8], 72);
                    wmma::mma_sync(acc, aq[k], bf, acc);
                }
                wmma::store_matrix_sync(&sc[(w * 16) * 132 + c * 16], acc, 132, wmma::mem_row_major);
            }
            __syncthreads();

            {
                int r = t >> 1;
                int c0 = (t & 1) << 6;
                bool rm = mr[r] != 0;
                const unsigned char* mjc = mj + cb * 128 + c0;
                float* p = &sc[r * 132 + c0];
                float lsum = 0.f;
#pragma unroll
                for (int j4 = 0; j4 < 16; j4++) {
                    float4 v = *(const float4*)(p + j4 * 4);
                    float4 e;
                    e.x = rm ? 1.f : (mjc[j4 * 4 + 0] ? 0.f : __expf(v.x * SCALE));
                    e.y = rm ? 1.f : (mjc[j4 * 4 + 1] ? 0.f : __expf(v.y * SCALE));
                    e.z = rm ? 1.f : (mjc[j4 * 4 + 2] ? 0.f : __expf(v.z * SCALE));
                    e.w = rm ? 1.f : (mjc[j4 * 4 + 3] ? 0.f : __expf(v.w * SCALE));
                    *(float4*)(p + j4 * 4) = e;
                    lsum += e.x + e.y + e.z + e.w;
                }
                float osum = __shfl_xor_sync(0xffffffffu, lsum, 1);
                if ((t & 1) == 0) rowsum[r] += lsum + osum;
            }
            __syncthreads();

#pragma unroll
            for (int i = 0; i < 16; i++) {
                int fi = t + (i << 8);
                int r = fi >> 5;
                int c4 = (fi & 31) << 2;
                *(float4*)(Wt + (size_t)r * NTOK + cb * 128 + c4) = *(const float4*)&sc[r * 132 + c4];
            }
            __syncthreads();
        }
    }

    if (t < 128)
        g_inv[((size_t)(b * HEADS + h) * NTOK) + row0 + t] = 1.f / rowsum[t];

    // ---------- Phase B: att = (e @ V) / rowsum ----------
    {
        CFrag acc[4];
#pragma unroll
        for (int dt = 0; dt < 4; dt++) wmma::fill_fragment(acc[dt], 0.f);

#pragma unroll
        for (int i = 0; i < 8; i++) {
            int fi = t + (i << 8);
            int r = fi >> 4;
            int d4 = (fi & 15) << 2;
            cp16(&kb[r * 72 + d4], Vg + (size_t)r * DIM + d4);
        }
        CP_COMMIT();

        for (int cb = 0; cb < 16; cb++) {
#pragma unroll
            for (int i = 0; i < 16; i++) {
                int fi = t + (i << 8);
                int r = fi >> 5;
                int c4 = (fi & 31) << 2;
                float4 v = *(const float4*)(Wt + (size_t)r * NTOK + cb * 128 + c4);
                *(float4*)&sc[r * 132 + c4] = tf4(v);
            }
            if (cb + 1 < 16) {
                float* dst = kb + ((cb + 1) & 1) * (128 * 72);
#pragma unroll
                for (int i = 0; i < 8; i++) {
                    int fi = t + (i << 8);
                    int r = fi >> 4;
                    int d4 = (fi & 15) << 2;
                    cp16(&dst[r * 72 + d4], Vg + (size_t)((cb + 1) * 128 + r) * DIM + d4);
                }
                CP_COMMIT();
                CP_WAIT(1);
            } else {
                CP_WAIT(0);
            }
            __syncthreads();
            float* buf = kb + (cb & 1) * (128 * 72);

#pragma unroll
            for (int k = 0; k < 16; k++) {
                AFrag ae;
                wmma::load_matrix_sync(ae, &sc[(w * 16) * 132 + k * 8], 132);
#pragma unroll
                for (int dt = 0; dt < 4; dt++) {
                    BFragRow bv;
                    wmma::load_matrix_sync(bv, &buf[(k * 8) * 72 + dt * 16], 72);
                    wmma::mma_sync(acc[dt], ae, bv, acc[dt]);
                }
            }
            __syncthreads();
        }

#pragma unroll
        for (int dt = 0; dt < 4; dt++)
            wmma::store_matrix_sync(&sc[(w * 16) * 132 + dt * 16], acc[dt], 132, wmma::mem_row_major);
        __syncthreads();
        {
            int r = t >> 1;
            int d0 = (t & 1) << 5;
            float inv = 1.f / rowsum[r];
            float* dst = att_out + ((size_t)b * NTOK + row0 + r) * CHID + h * DIM + d0;
#pragma unroll
            for (int j4 = 0; j4 < 8; j4++) {
                float4 v = *(const float4*)&sc[r * 132 + d0 + j4 * 4];
                v.x *= inv; v.y *= inv; v.z *= inv; v.w *= inv;
                *(float4*)(dst + j4 * 4) = v;
            }
        }
    }
}

// ---------------- normalize weights ----------------
__global__ __launch_bounds__(256) void normalize_w(float* __restrict__ w_out) {
    size_t nf4 = (size_t)BATCH * HEADS * NTOK * NTOK / 4;
    size_t stride = (size_t)gridDim.x * blockDim.x;
    for (size_t i = (size_t)blockIdx.x * blockDim.x + threadIdx.x; i < nf4; i += stride) {
        size_t fidx = i << 2;
        float inv = __ldg(&g_inv[fidx >> 11]);
        float4 v = *(float4*)(w_out + fidx);
        v.x *= inv; v.y *= inv; v.z *= inv; v.w *= inv;
        *(float4*)(w_out + fidx) = v;
    }
}

#define GEMM_SMEM (128 * 72 * 4)
#define ATT_SMEM ((128 * 72 + 2 * 128 * 72 + 128 * 132 + 128) * 4 + 2048 + 128)

extern "C" void kernel_launch(void* const* d_in, const int* in_sizes, int n_in,
                              void* d_out, int out_size) {
    (void)in_sizes; (void)n_in; (void)out_size;
    const float* X = (const float*)d_in[0];
    const float* W = (const float*)d_in[1];
    const void* mask = d_in[2];
    float* att = (float*)d_out;
    float* wts = (float*)d_out + (size_t)BATCH * NTOK * CHID;

    cudaFuncSetAttribute(attn_scores, cudaFuncAttributeMaxDynamicSharedMemorySize, ATT_SMEM);

    qkv_gemm<<<dim3(24, 32), 256, GEMM_SMEM>>>(X, W);
    attn_scores<<<dim3(16, HEADS, BATCH), 256, ATT_SMEM>>>(mask, att, wts);
    normalize_w<<<4096, 256>>>(wts);
}